// round 13
// baseline (speedup 1.0000x reference)
#include <cuda_runtime.h>
#include <math.h>

#define N_COLS 4096
#define TPB    256
#define EPS    1e-14f

// v held in registers across the barrier (zero epilogue v-traffic):
//   - 256 thr/row, 4 float4/thread x + 4 float4/thread v, fused ||v||^2
//   - ONE barrier; epilogue loads only bias (L1-hot)
//   - __ldcs on x, __stcs on out (single-use 256MB streams)
// out[i] = x[i] - (2*(x.v)/(||v||+eps)^2) * v[i] + bias[i]
__global__ void __launch_bounds__(TPB, 4)
householder_kernel(const float* __restrict__ x,
                   const float* __restrict__ v,
                   const float* __restrict__ bias,
                   float* __restrict__ out) {
    const int tid = threadIdx.x;
    const int w = tid >> 5, l = tid & 31;
    const int row = blockIdx.x;

    const float4* __restrict__ xr = (const float4*)(x + (size_t)row * N_COLS);
    const float4* __restrict__ vr = (const float4*)v;
    const float4* __restrict__ br = (const float4*)bias;
    float4* __restrict__       orow = (float4*)(out + (size_t)row * N_COLS);

    __shared__ float red_d[TPB / 32];
    __shared__ float red_n[TPB / 32];

    // ---- single pass: load row + v (kept in regs), accumulate dots ----
    float4 xv[4], vv[4];
    float dot = 0.0f, vn = 0.0f;
    #pragma unroll
    for (int j = 0; j < 4; j++) {
        const int idx = tid + j * TPB;     // coalesced 128B per warp
        xv[j] = __ldcs(&xr[idx]);          // streaming: x is single-use
        vv[j] = vr[idx];                   // default policy: v is L1/L2-hot
        dot = fmaf(xv[j].x, vv[j].x, dot);
        dot = fmaf(xv[j].y, vv[j].y, dot);
        dot = fmaf(xv[j].z, vv[j].z, dot);
        dot = fmaf(xv[j].w, vv[j].w, dot);
        vn  = fmaf(vv[j].x, vv[j].x, vn);
        vn  = fmaf(vv[j].y, vv[j].y, vn);
        vn  = fmaf(vv[j].z, vv[j].z, vn);
        vn  = fmaf(vv[j].w, vv[j].w, vn);
    }

    #pragma unroll
    for (int o = 16; o > 0; o >>= 1) {
        dot += __shfl_xor_sync(0xffffffffu, dot, o);
        vn  += __shfl_xor_sync(0xffffffffu, vn,  o);
    }
    if (l == 0) { red_d[w] = dot; red_n[w] = vn; }
    __syncthreads();                        // the ONLY barrier

    // every thread finishes the reduction itself (broadcast LDS)
    float td = 0.0f, tn = 0.0f;
    #pragma unroll
    for (int i = 0; i < TPB / 32; i++) { td += red_d[i]; tn += red_n[i]; }
    const float s = 1.0f / (sqrtf(tn) + EPS);
    const float coef = 2.0f * td * s * s;

    // ---- epilogue: v already in regs, only bias loads, streaming store ----
    #pragma unroll
    for (int j = 0; j < 4; j++) {
        const int idx = tid + j * TPB;
        float4 bb = br[idx];
        float4 o4;
        o4.x = fmaf(-coef, vv[j].x, xv[j].x) + bb.x;
        o4.y = fmaf(-coef, vv[j].y, xv[j].y) + bb.y;
        o4.z = fmaf(-coef, vv[j].z, xv[j].z) + bb.z;
        o4.w = fmaf(-coef, vv[j].w, xv[j].w) + bb.w;
        __stcs(&orow[idx], o4);            // streaming: out never re-read
    }
}

extern "C" void kernel_launch(void* const* d_in, const int* in_sizes, int n_in,
                              void* d_out, int out_size) {
    const float* x    = (const float*)d_in[0];   // [16384, 4096]
    const float* v    = (const float*)d_in[1];   // [4096, 1]
    const float* bias = (const float*)d_in[2];   // [4096]
    float* out = (float*)d_out;

    const int n_rows = in_sizes[0] / N_COLS;     // 16384

    householder_kernel<<<n_rows, TPB>>>(x, v, bias, out);
}